// round 7
// baseline (speedup 1.0000x reference)
#include <cuda_runtime.h>
#include <math_constants.h>

// Problem constants
#define B_   32
#define S_   2048
#define D_   1024
#define A_   512
#define BS_  (B_ * S_)          // 65536 rows

// GEMM tiling
#define BM   128
#define BN   64
#define BKK  16
#define NCHUNKS (A_ / BN)       // 8
#define SCHUNKS 16              // S split for the output stage

// Device-global scratch (allocation-free rule)
__device__ float g_mask[BS_];
__device__ float g_scores[BS_];
__device__ float g_alphas[BS_];
__device__ float g_partial[SCHUNKS * B_ * D_];   // 2 MB

// ---------------------------------------------------------------------------
// Kernel 1: mask[b,s] = (sum_d x[b,s,d] != 0) ? 1 : 0
// One warp per row, float4 loads. 8 rows per block.
// ---------------------------------------------------------------------------
__global__ void mask_kernel(const float* __restrict__ x) {
    int row  = blockIdx.x * 8 + (threadIdx.x >> 5);
    int lane = threadIdx.x & 31;
    const float4* xr = reinterpret_cast<const float4*>(x + (size_t)row * D_);
    float s = 0.0f;
#pragma unroll
    for (int i = 0; i < 8; ++i) {
        float4 v = xr[lane + 32 * i];
        s += (v.x + v.y) + (v.z + v.w);
    }
#pragma unroll
    for (int off = 16; off > 0; off >>= 1)
        s += __shfl_down_sync(0xffffffffu, s, off);
    if (lane == 0)
        g_mask[row] = (s != 0.0f) ? 1.0f : 0.0f;
}

// ---------------------------------------------------------------------------
// Kernel 2: scores[row] = sum_a tanh( gru[row,:] . W[:,a] ) * u[a]
// Tiled fp32 GEMM: BM=128 rows x BN=64 cols per pass, BK=16, 256 threads,
// 8x4 register microtile per thread. N-chunk loop inside the block so the
// tanh*u reduction accumulates in registers; final shfl-reduce over the 16
// threads sharing each row.
// ---------------------------------------------------------------------------
__global__ __launch_bounds__(256)
void score_kernel(const float* __restrict__ gru,
                  const float* __restrict__ W,
                  const float* __restrict__ u) {
    __shared__ float As[BKK][BM + 4];   // padded: conflict-free transposed stores
    __shared__ float Bs[BKK][BN];

    const int tid = threadIdx.x;
    const int tx  = tid & 15;           // 16 column groups
    const int ty  = tid >> 4;           // 16 row groups
    const int m0  = blockIdx.x * BM;
    const int rowbase = ty * 8;
    const int colbase = tx * 4;

    float score[8];
#pragma unroll
    for (int i = 0; i < 8; ++i) score[i] = 0.0f;

    // B-tile load indices (constant across iterations)
    const int bk = tid >> 4;            // 0..15
    const int bn = (tid & 15) * 4;      // 0..60

    for (int nc = 0; nc < NCHUNKS; ++nc) {
        const int n0 = nc * BN;
        float acc[8][4];
#pragma unroll
        for (int i = 0; i < 8; ++i)
#pragma unroll
            for (int j = 0; j < 4; ++j) acc[i][j] = 0.0f;

        for (int k0 = 0; k0 < D_; k0 += BKK) {
            // Load A tile (128 x 16), transposed into smem
#pragma unroll
            for (int l = 0; l < 2; ++l) {
                int f  = tid + l * 256;     // 0..511 float4 slots
                int r  = f >> 2;            // row 0..127
                int kq = f & 3;             // which float4 along k
                float4 v = *reinterpret_cast<const float4*>(
                    gru + (size_t)(m0 + r) * D_ + k0 + kq * 4);
                As[kq * 4 + 0][r] = v.x;
                As[kq * 4 + 1][r] = v.y;
                As[kq * 4 + 2][r] = v.z;
                As[kq * 4 + 3][r] = v.w;
            }
            // Load B tile (16 x 64)
            *reinterpret_cast<float4*>(&Bs[bk][bn]) =
                *reinterpret_cast<const float4*>(W + (size_t)(k0 + bk) * A_ + n0 + bn);
            __syncthreads();

#pragma unroll
            for (int kk = 0; kk < BKK; ++kk) {
                float a[8], b[4];
#pragma unroll
                for (int i = 0; i < 8; ++i) a[i] = As[kk][rowbase + i];
#pragma unroll
                for (int j = 0; j < 4; ++j) b[j] = Bs[kk][colbase + j];
#pragma unroll
                for (int i = 0; i < 8; ++i)
#pragma unroll
                    for (int j = 0; j < 4; ++j)
                        acc[i][j] = fmaf(a[i], b[j], acc[i][j]);
            }
            __syncthreads();
        }

        // Epilogue for this N chunk: score += tanh(acc) * u
        float ub[4];
#pragma unroll
        for (int j = 0; j < 4; ++j) ub[j] = __ldg(&u[n0 + colbase + j]);
#pragma unroll
        for (int i = 0; i < 8; ++i) {
            float s = 0.0f;
#pragma unroll
            for (int j = 0; j < 4; ++j) s += tanhf(acc[i][j]) * ub[j];
            score[i] += s;
        }
    }

    // Reduce each row's partial score across the 16 tx lanes (width-16 shfl)
#pragma unroll
    for (int i = 0; i < 8; ++i) {
        float v = score[i];
#pragma unroll
        for (int off = 8; off > 0; off >>= 1)
            v += __shfl_down_sync(0xffffffffu, v, off, 16);
        if (tx == 0) {
            int row = m0 + rowbase + i;
            g_scores[row] = (g_mask[row] != 0.0f) ? v : -1e9f;
        }
    }
}

// ---------------------------------------------------------------------------
// Kernel 3: softmax over S per batch. One block per batch, 256 threads x 8.
// ---------------------------------------------------------------------------
__global__ void softmax_kernel() {
    __shared__ float red[256];
    const int b = blockIdx.x;
    const int t = threadIdx.x;
    const float* sc = g_scores + (size_t)b * S_;
    float*       al = g_alphas + (size_t)b * S_;

    float v[8];
    float m = -CUDART_INF_F;
#pragma unroll
    for (int i = 0; i < 8; ++i) {
        v[i] = sc[t + 256 * i];
        m = fmaxf(m, v[i]);
    }
    red[t] = m;
    __syncthreads();
    for (int s = 128; s > 0; s >>= 1) {
        if (t < s) red[t] = fmaxf(red[t], red[t + s]);
        __syncthreads();
    }
    m = red[0];
    __syncthreads();

    float sum = 0.0f;
#pragma unroll
    for (int i = 0; i < 8; ++i) {
        v[i] = expf(v[i] - m);
        sum += v[i];
    }
    red[t] = sum;
    __syncthreads();
    for (int s = 128; s > 0; s >>= 1) {
        if (t < s) red[t] += red[t + s];
        __syncthreads();
    }
    float inv = 1.0f / red[0];
#pragma unroll
    for (int i = 0; i < 8; ++i)
        al[t + 256 * i] = v[i] * inv;
}

// ---------------------------------------------------------------------------
// Kernel 4: partial weighted sums. Grid (SCHUNKS, B). Each block: 256 threads,
// one float4 of D per thread, loops its S chunk. Deterministic (no atomics).
// ---------------------------------------------------------------------------
__global__ void out_partial_kernel(const float* __restrict__ gru) {
    const int sc = blockIdx.x;          // 0..15
    const int b  = blockIdx.y;          // 0..31
    const int t  = threadIdx.x;         // 0..255 -> float4 over D
    const int schunk = S_ / SCHUNKS;    // 128

    const float*  al = g_alphas + (size_t)b * S_ + sc * schunk;
    const float4* g  = reinterpret_cast<const float4*>(
        gru + ((size_t)b * S_ + (size_t)sc * schunk) * D_);

    float4 acc = make_float4(0.f, 0.f, 0.f, 0.f);
    for (int s = 0; s < schunk; ++s) {
        float a  = al[s];
        float4 v = g[(size_t)s * (D_ / 4) + t];
        acc.x = fmaf(v.x, a, acc.x);
        acc.y = fmaf(v.y, a, acc.y);
        acc.z = fmaf(v.z, a, acc.z);
        acc.w = fmaf(v.w, a, acc.w);
    }
    reinterpret_cast<float4*>(g_partial)[(size_t)sc * (B_ * D_ / 4) + b * (D_ / 4) + t] = acc;
}

// ---------------------------------------------------------------------------
// Kernel 5: reduce the SCHUNKS partials into d_out [B, D].
// ---------------------------------------------------------------------------
__global__ void out_reduce_kernel(float* __restrict__ out) {
    int idx = blockIdx.x * blockDim.x + threadIdx.x;   // over B_*D_
    float s = 0.0f;
#pragma unroll
    for (int c = 0; c < SCHUNKS; ++c)
        s += g_partial[(size_t)c * (B_ * D_) + idx];
    out[idx] = s;
}

// ---------------------------------------------------------------------------
extern "C" void kernel_launch(void* const* d_in, const int* in_sizes, int n_in,
                              void* d_out, int out_size) {
    const float* x   = (const float*)d_in[0];
    const float* gru = (const float*)d_in[1];
    const float* W   = (const float*)d_in[2];
    const float* u   = (const float*)d_in[3];
    float* out = (float*)d_out;

    mask_kernel<<<BS_ / 8, 256>>>(x);
    score_kernel<<<BS_ / BM, 256>>>(gru, W, u);
    softmax_kernel<<<B_, 256>>>();
    out_partial_kernel<<<dim3(SCHUNKS, B_), 256>>>(gru);
    out_reduce_kernel<<<(B_ * D_) / 256, 256>>>(out);
}

// round 9
// speedup vs baseline: 3.7008x; 3.7008x over previous
#include <cuda_runtime.h>
#include <math_constants.h>
#include <cstdint>

// Problem constants
#define B_   32
#define S_   2048
#define D_   1024
#define A_   512
#define BS_  (B_ * S_)          // 65536 rows

// GEMM tiling
#define BM   128
#define BN   128
#define BKK  32
#define NCH  (A_ / BN)          // 4 N chunks
#define KIT  (D_ / BKK)         // 32 k iterations
#define SCHUNKS 16

// SMEM layout (bytes, relative to 1024-aligned base)
// 3 stages x (A 16KB + B 16KB) = 96KB, then u (2KB), then scorebuf (1KB)
#define STG_BYTES 32768
#define SM_U      98304
#define SM_SB     100352
#define SMEM_BYTES (1024 + 101376)

// Device-global scratch (allocation-free rule)
__device__ float g_mask[BS_];
__device__ float g_scores[BS_];
__device__ float g_alphas[BS_];
__device__ float g_partial[SCHUNKS * B_ * D_];
__device__ float g_Wt[A_ * D_];       // W transposed: [A, D] rows are K-major

// ---------------------------------------------------------------------------
// PTX helpers
// ---------------------------------------------------------------------------
__device__ __forceinline__ uint32_t smem_u32(const void* p) {
    uint32_t a;
    asm("{ .reg .u64 t; cvta.to.shared.u64 t, %1; cvt.u32.u64 %0, t; }"
        : "=r"(a) : "l"(p));
    return a;
}
__device__ __forceinline__ void cp16(uint32_t dst, const void* src) {
    asm volatile("cp.async.cg.shared.global [%0], [%1], 16;\n"
                 :: "r"(dst), "l"(src));
}
#define CP_COMMIT() asm volatile("cp.async.commit_group;\n" ::: "memory")
#define CP_WAIT1()  asm volatile("cp.async.wait_group 1;\n" ::: "memory")

// swizzled 16B-chunk address: 128B rows, chunk XOR row%8 (conflict-free LDSM)
__device__ __forceinline__ uint32_t sw(uint32_t base, int row, int chunk) {
    return base + (uint32_t)(row * 128) + (uint32_t)(((chunk ^ (row & 7)) & 7) * 16);
}
__device__ __forceinline__ void ldsm4(uint32_t addr, uint32_t& r0, uint32_t& r1,
                                      uint32_t& r2, uint32_t& r3) {
    asm volatile("ldmatrix.sync.aligned.m8n8.x4.shared.b16 {%0,%1,%2,%3}, [%4];"
                 : "=r"(r0), "=r"(r1), "=r"(r2), "=r"(r3) : "r"(addr));
}
__device__ __forceinline__ uint32_t to_tf32(uint32_t x) {
    uint32_t y;
    asm("cvt.rna.tf32.f32 %0, %1;" : "=r"(y) : "r"(x));
    return y;
}
__device__ __forceinline__ void mma_tf32(float* d, const uint32_t* a, const uint32_t* b) {
    asm volatile(
        "mma.sync.aligned.m16n8k8.row.col.f32.tf32.tf32.f32 "
        "{%0,%1,%2,%3}, {%4,%5,%6,%7}, {%8,%9}, {%0,%1,%2,%3};"
        : "+f"(d[0]), "+f"(d[1]), "+f"(d[2]), "+f"(d[3])
        : "r"(a[0]), "r"(a[1]), "r"(a[2]), "r"(a[3]), "r"(b[0]), "r"(b[1]));
}

// ---------------------------------------------------------------------------
// Kernel 0: transpose W [D, A] -> g_Wt [A, D]
// ---------------------------------------------------------------------------
__global__ void transpose_kernel(const float* __restrict__ W) {
    __shared__ float t[32][33];
    int n0 = blockIdx.x * 32;
    int k0 = blockIdx.y * 32;
    int tx = threadIdx.x, ty = threadIdx.y;
#pragma unroll
    for (int i = 0; i < 32; i += 8)
        t[ty + i][tx] = W[(size_t)(k0 + ty + i) * A_ + n0 + tx];
    __syncthreads();
#pragma unroll
    for (int i = 0; i < 32; i += 8)
        g_Wt[(size_t)(n0 + ty + i) * D_ + k0 + tx] = t[tx][ty + i];
}

// ---------------------------------------------------------------------------
// Kernel 1: mask[b,s] = (sum_d x[b,s,d] != 0) ? 1 : 0
// ---------------------------------------------------------------------------
__global__ void mask_kernel(const float* __restrict__ x) {
    int row  = blockIdx.x * 8 + (threadIdx.x >> 5);
    int lane = threadIdx.x & 31;
    const float4* xr = reinterpret_cast<const float4*>(x + (size_t)row * D_);
    float s = 0.0f;
#pragma unroll
    for (int i = 0; i < 8; ++i) {
        float4 v = xr[lane + 32 * i];
        s += (v.x + v.y) + (v.z + v.w);
    }
#pragma unroll
    for (int off = 16; off > 0; off >>= 1)
        s += __shfl_down_sync(0xffffffffu, s, off);
    if (lane == 0)
        g_mask[row] = (s != 0.0f) ? 1.0f : 0.0f;
}

// ---------------------------------------------------------------------------
// Tile loader: 128 rows x 32 fp32 (8 x 16B chunks per row), swizzled
// ---------------------------------------------------------------------------
__device__ __forceinline__ void load_tile(const float* __restrict__ src,
                                          uint32_t dst, int tid) {
#pragma unroll
    for (int i = 0; i < 4; ++i) {
        int f = tid + 256 * i;
        int r = f >> 3, q = f & 7;
        cp16(sw(dst, r, q), src + (size_t)r * D_ + q * 4);
    }
}

// ---------------------------------------------------------------------------
// Kernel 2: tf32 mma.sync GEMM + fused tanh*u epilogue -> g_scores
// 256 threads, BM=128, BN=128 (x4 chunks), BK=32, triple-buffered cp.async.
// ---------------------------------------------------------------------------
__global__ __launch_bounds__(256)
void score_kernel(const float* __restrict__ gru, const float* __restrict__ u) {
    extern __shared__ char smraw[];
    char* s0p = (char*)(((uintptr_t)smraw + 1023u) & ~(uintptr_t)1023u);
    const uint32_t s0 = smem_u32(s0p);
    float* su = (float*)(s0p + SM_U);
    float* sb = (float*)(s0p + SM_SB);   // [2][128]

    const int tid  = threadIdx.x;
    const int lane = tid & 31;
    const int wid  = tid >> 5;
    const int wm   = wid & 3;            // 4 warps along M (32 rows each)
    const int wn   = wid >> 2;           // 2 warps along N (64 cols each)
    const int m0   = blockIdx.x * BM;

    // u -> smem (512 floats)
    reinterpret_cast<float2*>(su)[tid] = reinterpret_cast<const float2*>(u)[tid];

    // Fragment addresses (constant part)
    const int arow = wm * 32 + (lane & 15);          // + mt*16
    const int achk = (lane >> 4);                    // + ks*2
    const int brow = wn * 64 + (lane & 7) + ((lane >> 4) << 3);  // + pair*16
    const int bchk = ((lane >> 3) & 1);              // + ks*2

    float score[2][2] = {{0.f, 0.f}, {0.f, 0.f}};    // [mt][rowhalf]

    for (int nc = 0; nc < NCH; ++nc) {
        const float* gA = gru  + (size_t)m0 * D_;
        const float* gB = g_Wt + (size_t)(nc * BN) * D_;

        float acc[2][8][4];
#pragma unroll
        for (int mt = 0; mt < 2; ++mt)
#pragma unroll
            for (int nt = 0; nt < 8; ++nt)
#pragma unroll
                for (int j = 0; j < 4; ++j) acc[mt][nt][j] = 0.0f;

        // Prologue: stages 0 and 1
        load_tile(gA, s0, tid);
        load_tile(gB, s0 + 16384, tid);
        CP_COMMIT();
        load_tile(gA + BKK, s0 + STG_BYTES, tid);
        load_tile(gB + BKK, s0 + STG_BYTES + 16384, tid);
        CP_COMMIT();

        for (int kt = 0; kt < KIT; ++kt) {
            CP_WAIT1();
            __syncthreads();

            // Prefetch kt+2 into stage (kt+2)%3 (last read two iters ago)
            if (kt + 2 < KIT) {
                uint32_t ds = s0 + (uint32_t)(((kt + 2) % 3) * STG_BYTES);
                load_tile(gA + (kt + 2) * BKK, ds, tid);
                load_tile(gB + (kt + 2) * BKK, ds + 16384, tid);
            }
            CP_COMMIT();

            const uint32_t sA = s0 + (uint32_t)((kt % 3) * STG_BYTES);
            const uint32_t sB = sA + 16384;

#pragma unroll
            for (int ks = 0; ks < 4; ++ks) {
                uint32_t a[2][4], b[4][4];
#pragma unroll
                for (int mt = 0; mt < 2; ++mt) {
                    ldsm4(sw(sA, arow + mt * 16, ks * 2 + achk),
                          a[mt][0], a[mt][1], a[mt][2], a[mt][3]);
#pragma unroll
                    for (int j = 0; j < 4; ++j) a[mt][j] = to_tf32(a[mt][j]);
                }
#pragma unroll
                for (int pr = 0; pr < 4; ++pr) {
                    ldsm4(sw(sB, brow + pr * 16, ks * 2 + bchk),
                          b[pr][0], b[pr][1], b[pr][2], b[pr][3]);
#pragma unroll
                    for (int j = 0; j < 4; ++j) b[pr][j] = to_tf32(b[pr][j]);
                }
#pragma unroll
                for (int mt = 0; mt < 2; ++mt)
#pragma unroll
                    for (int pr = 0; pr < 4; ++pr) {
                        mma_tf32(acc[mt][pr * 2 + 0], a[mt], &b[pr][0]);
                        mma_tf32(acc[mt][pr * 2 + 1], a[mt], &b[pr][2]);
                    }
            }
            __syncthreads();   // all warps done with stage kt%3 before refill
        }

        // Epilogue: score += tanh(acc) * u  (c0,c1: row lane/4; c2,c3: +8)
#pragma unroll
        for (int mt = 0; mt < 2; ++mt)
#pragma unroll
            for (int nt = 0; nt < 8; ++nt) {
                int col = nc * BN + wn * 64 + nt * 8 + (lane & 3) * 2;
                float u0 = su[col], u1 = su[col + 1];
                score[mt][0] += tanhf(acc[mt][nt][0]) * u0 + tanhf(acc[mt][nt][1]) * u1;
                score[mt][1] += tanhf(acc[mt][nt][2]) * u0 + tanhf(acc[mt][nt][3]) * u1;
            }
    }

    // Reduce over the 4 lanes sharing each row (cols within warp)
#pragma unroll
    for (int mt = 0; mt < 2; ++mt)
#pragma unroll
        for (int h = 0; h < 2; ++h) {
            float v = score[mt][h];
            v += __shfl_xor_sync(0xffffffffu, v, 1);
            v += __shfl_xor_sync(0xffffffffu, v, 2);
            score[mt][h] = v;
        }
    if ((lane & 3) == 0) {
#pragma unroll
        for (int mt = 0; mt < 2; ++mt)
#pragma unroll
            for (int h = 0; h < 2; ++h) {
                int r = wm * 32 + mt * 16 + (lane >> 2) + h * 8;
                sb[wn * 128 + r] = score[mt][h];
            }
    }
    __syncthreads();
    if (tid < 128) {
        int row = m0 + tid;
        float s = sb[tid] + sb[128 + tid];
        g_scores[row] = (g_mask[row] != 0.0f) ? s : -1e9f;
    }
}

// ---------------------------------------------------------------------------
// Kernel 3: softmax over S per batch
// ---------------------------------------------------------------------------
__global__ void softmax_kernel() {
    __shared__ float red[256];
    const int b = blockIdx.x;
    const int t = threadIdx.x;
    const float* sc = g_scores + (size_t)b * S_;
    float*       al = g_alphas + (size_t)b * S_;

    float v[8];
    float m = -CUDART_INF_F;
#pragma unroll
    for (int i = 0; i < 8; ++i) {
        v[i] = sc[t + 256 * i];
        m = fmaxf(m, v[i]);
    }
    red[t] = m;
    __syncthreads();
    for (int s = 128; s > 0; s >>= 1) {
        if (t < s) red[t] = fmaxf(red[t], red[t + s]);
        __syncthreads();
    }
    m = red[0];
    __syncthreads();

    float sum = 0.0f;
#pragma unroll
    for (int i = 0; i < 8; ++i) {
        v[i] = expf(v[i] - m);
        sum += v[i];
    }
    red[t] = sum;
    __syncthreads();
    for (int s = 128; s > 0; s >>= 1) {
        if (t < s) red[t] += red[t + s];
        __syncthreads();
    }
    float inv = 1.0f / red[0];
#pragma unroll
    for (int i = 0; i < 8; ++i)
        al[t + 256 * i] = v[i] * inv;
}

// ---------------------------------------------------------------------------
// Kernel 4: partial weighted sums (deterministic, no atomics)
// ---------------------------------------------------------------------------
__global__ void out_partial_kernel(const float* __restrict__ gru) {
    const int sc = blockIdx.x;
    const int b  = blockIdx.y;
    const int t  = threadIdx.x;
    const int schunk = S_ / SCHUNKS;

    const float*  al = g_alphas + (size_t)b * S_ + sc * schunk;
    const float4* g  = reinterpret_cast<const float4*>(
        gru + ((size_t)b * S_ + (size_t)sc * schunk) * D_);

    float4 acc = make_float4(0.f, 0.f, 0.f, 0.f);
    for (int s = 0; s < schunk; ++s) {
        float a  = al[s];
        float4 v = g[(size_t)s * (D_ / 4) + t];
        acc.x = fmaf(v.x, a, acc.x);
        acc.y = fmaf(v.y, a, acc.y);
        acc.z = fmaf(v.z, a, acc.z);
        acc.w = fmaf(v.w, a, acc.w);
    }
    reinterpret_cast<float4*>(g_partial)[(size_t)sc * (B_ * D_ / 4) + b * (D_ / 4) + t] = acc;
}

// ---------------------------------------------------------------------------
// Kernel 5: reduce partials -> d_out [B, D]
// ---------------------------------------------------------------------------
__global__ void out_reduce_kernel(float* __restrict__ out) {
    int idx = blockIdx.x * blockDim.x + threadIdx.x;
    float s = 0.0f;
#pragma unroll
    for (int c = 0; c < SCHUNKS; ++c)
        s += g_partial[(size_t)c * (B_ * D_) + idx];
    out[idx] = s;
}

// ---------------------------------------------------------------------------
extern "C" void kernel_launch(void* const* d_in, const int* in_sizes, int n_in,
                              void* d_out, int out_size) {
    const float* x   = (const float*)d_in[0];
    const float* gru = (const float*)d_in[1];
    const float* W   = (const float*)d_in[2];
    const float* u   = (const float*)d_in[3];
    float* out = (float*)d_out;

    cudaFuncSetAttribute(score_kernel,
                         cudaFuncAttributeMaxDynamicSharedMemorySize, SMEM_BYTES);

    transpose_kernel<<<dim3(A_ / 32, D_ / 32), dim3(32, 8)>>>(W);
    mask_kernel<<<BS_ / 8, 256>>>(x);
    score_kernel<<<BS_ / BM, 256, SMEM_BYTES>>>(gru, u);
    softmax_kernel<<<B_, 256>>>();
    out_partial_kernel<<<dim3(SCHUNKS, B_), 256>>>(gru);
    out_reduce_kernel<<<(B_ * D_) / 256, 256>>>(out);
}